// round 13
// baseline (speedup 1.0000x reference)
#include <cuda_runtime.h>
#include <cstdint>

// ---------------------------------------------------------------------------
// XPool cross-modal attention, GB300 round 13: R12 + split-K.
// attn/Wo/Wl GEMMs split K in half (2x CTAs -> 2 CTAs/SM co-residency);
// partial sums fused into LN2 (addx), LN3 (addx+addx2), and one small
// sum+round kernel for attn. Deterministic (no atomics).
// ---------------------------------------------------------------------------

#define EMBED 512
#define HEADS 2
#define HDIM  256
#define TTOK  4096
#define VTOK  768
#define FR    12
#define NV    64

#define APAD   20
#define STG_W  (128 * APAD)
#define NSTAGE 4
#define SMEM_BYTES (2 * NSTAGE * STG_W * 4)   // 81920

// ------------------------------- scratch ----------------------------------
__device__ float g_tn   [TTOK*EMBED];
__device__ float g_vn   [VTOK*EMBED];
__device__ float g_q    [TTOK*EMBED];
__device__ float g_k    [VTOK*EMBED];
__device__ float g_vt   [EMBED*VTOK];
__device__ float g_s    [HEADS*TTOK*VTOK];
__device__ float g_attn [TTOK*EMBED];
__device__ float g_attnP[2*TTOK*EMBED];       // attn split-K partials
__device__ float g_opreP[2*TTOK*EMBED];       // Wo split-K partials
__device__ float g_o    [TTOK*EMBED];
__device__ float g_or   [TTOK*EMBED];
__device__ float g_linP [2*TTOK*EMBED];       // Wl split-K partials
__device__ float g_wqr  [EMBED*EMBED];
__device__ float g_wkr  [EMBED*EMBED];
__device__ float g_wvr  [EMBED*EMBED];
__device__ float g_wor  [EMBED*EMBED];
__device__ float g_wlr  [EMBED*EMBED];

__device__ __forceinline__ uint32_t f2tf32(float x) {
    uint32_t u;
    asm("cvt.rna.tf32.f32 %0, %1;" : "=r"(u) : "f"(x));
    return u;
}
__device__ __forceinline__ float roundtf(float x) {
    return __uint_as_float(f2tf32(x));
}

#define CP16(dst, src) \
    asm volatile("cp.async.cg.shared.global [%0], [%1], 16;" \
        :: "r"(dst), "l"(src) : "memory")
#define CP_COMMIT() asm volatile("cp.async.commit_group;" ::: "memory")
#define CP_WAIT2()  asm volatile("cp.async.wait_group 2;" ::: "memory")
#define CP_WAIT0()  asm volatile("cp.async.wait_group 0;" ::: "memory")

__device__ __forceinline__ void ldsm4(uint32_t& r0, uint32_t& r1,
                                      uint32_t& r2, uint32_t& r3,
                                      uint32_t addr) {
    asm volatile("ldmatrix.sync.aligned.m8n8.x4.shared.b16 {%0,%1,%2,%3}, [%4];"
        : "=r"(r0), "=r"(r1), "=r"(r2), "=r"(r3) : "r"(addr));
}

// ---------------------------------------------------------------------------
// 128x128 NT tf32 GEMM tile body (R12 engine: BK=16, 4-stage cp.async,
// ldmatrix fragments). writeMode: 0 plain, 1 rounded, 2 rounded transposed.
// ---------------------------------------------------------------------------
__device__ __forceinline__ void gemm_tile_body(
    const float* __restrict__ A, int lda,
    const float* __restrict__ B, int ldb,
    float* __restrict__ C, int ldc,
    const float* __restrict__ bias,
    float alpha, int K, int bm, int bn, int writeMode)
{
    extern __shared__ uint32_t sm[];
    uint32_t* Asw = sm;
    uint32_t* Bsw = sm + NSTAGE * STG_W;

    const int tid  = threadIdx.x;
    const int lane = tid & 31;
    const int warp = tid >> 5;
    const int wm   = (warp >> 1) * 32;
    const int wn   = (warp & 1) * 64;
    const int gid  = lane >> 2;
    const int tig  = lane & 3;

    const int prow = tid & 127;
    const int pkc  = (tid >> 7) * 8;
    const float* Ap = A + (size_t)(bm + prow) * lda + pkc;
    const float* Bp = B + (size_t)(bn + prow) * ldb + pkc;

    const uint32_t aBase = (uint32_t)__cvta_generic_to_shared(Asw)
                         + (uint32_t)(prow * APAD + pkc) * 4u;
    const uint32_t bBase = (uint32_t)__cvta_generic_to_shared(Bsw)
                         + (uint32_t)(prow * APAD + pkc) * 4u;

    const int aRow = (lane & 7) + ((lane >> 3) & 1) * 8;
    const int aKh  = ((lane >> 4) & 1) * 4;
    const uint32_t aFragBase = (uint32_t)__cvta_generic_to_shared(Asw)
        + (uint32_t)(((wm + aRow) * APAD) + aKh) * 4u;
    const int bRow = (lane & 7) + ((lane >> 4) & 1) * 8;
    const int bKh  = ((lane >> 3) & 1) * 4;
    const uint32_t bFragBase = (uint32_t)__cvta_generic_to_shared(Bsw)
        + (uint32_t)(((wn + bRow) * APAD) + bKh) * 4u;

    float acc[2][8][4];
#pragma unroll
    for (int mi = 0; mi < 2; mi++)
#pragma unroll
        for (int ni = 0; ni < 8; ni++)
#pragma unroll
            for (int r = 0; r < 4; r++) acc[mi][ni][r] = 0.0f;

    const int nsteps = K / 16;

#pragma unroll
    for (int s = 0; s < NSTAGE - 1; s++) {
        const uint32_t ad = aBase + (uint32_t)(s * STG_W) * 4u;
        const uint32_t bd = bBase + (uint32_t)(s * STG_W) * 4u;
        CP16(ad,      Ap + s * 16);
        CP16(ad + 16, Ap + s * 16 + 4);
        CP16(bd,      Bp + s * 16);
        CP16(bd + 16, Bp + s * 16 + 4);
        CP_COMMIT();
    }

#pragma unroll 1
    for (int step = 0; step < nsteps; step++) {
        const int cur = step & (NSTAGE - 1);
        CP_WAIT2();
        __syncthreads();

        const uint32_t aF = aFragBase + (uint32_t)(cur * STG_W) * 4u;
        const uint32_t bF = bFragBase + (uint32_t)(cur * STG_W) * 4u;

#pragma unroll
        for (int kk = 0; kk < 2; kk++) {
            const uint32_t kOff = (uint32_t)(kk * 8) * 4u;
            uint32_t af[2][4];
#pragma unroll
            for (int mi = 0; mi < 2; mi++)
                ldsm4(af[mi][0], af[mi][1], af[mi][2], af[mi][3],
                      aF + kOff + (uint32_t)(mi * 16 * APAD) * 4u);
            uint32_t bf[8][2];
#pragma unroll
            for (int j = 0; j < 4; j++) {
                ldsm4(bf[2*j][0], bf[2*j][1], bf[2*j+1][0], bf[2*j+1][1],
                      bF + kOff + (uint32_t)(j * 16 * APAD) * 4u);
            }
#pragma unroll
            for (int mi = 0; mi < 2; mi++)
#pragma unroll
                for (int ni = 0; ni < 8; ni++) {
                    asm("mma.sync.aligned.m16n8k8.row.col.f32.tf32.tf32.f32 "
                        "{%0,%1,%2,%3}, {%4,%5,%6,%7}, {%8,%9}, {%0,%1,%2,%3};"
                        : "+f"(acc[mi][ni][0]), "+f"(acc[mi][ni][1]),
                          "+f"(acc[mi][ni][2]), "+f"(acc[mi][ni][3])
                        : "r"(af[mi][0]), "r"(af[mi][1]),
                          "r"(af[mi][2]), "r"(af[mi][3]),
                          "r"(bf[ni][0]), "r"(bf[ni][1]));
                }
        }

        const int pf = step + NSTAGE - 1;
        if (pf < nsteps) {
            const int ps = pf & (NSTAGE - 1);
            const uint32_t ad = aBase + (uint32_t)(ps * STG_W) * 4u;
            const uint32_t bd = bBase + (uint32_t)(ps * STG_W) * 4u;
            CP16(ad,      Ap + pf * 16);
            CP16(ad + 16, Ap + pf * 16 + 4);
            CP16(bd,      Bp + pf * 16);
            CP16(bd + 16, Bp + pf * 16 + 4);
        }
        CP_COMMIT();
    }
    CP_WAIT0();

#pragma unroll
    for (int mi = 0; mi < 2; mi++) {
        const int r0 = bm + wm + mi * 16 + gid;
#pragma unroll
        for (int ni = 0; ni < 8; ni++) {
            const int c0 = bn + wn + ni * 8 + tig * 2;
            float bx = 0.0f, by = 0.0f;
            if (bias) { bx = bias[c0]; by = bias[c0 + 1]; }
            float2 v0, v1;
            v0.x = alpha * acc[mi][ni][0] + bx;
            v0.y = alpha * acc[mi][ni][1] + by;
            v1.x = alpha * acc[mi][ni][2] + bx;
            v1.y = alpha * acc[mi][ni][3] + by;
            if (writeMode == 0) {
                *(float2*)(C + (size_t)r0 * ldc + c0)       = v0;
                *(float2*)(C + (size_t)(r0 + 8) * ldc + c0) = v1;
            } else if (writeMode == 1) {
                v0.x = roundtf(v0.x); v0.y = roundtf(v0.y);
                v1.x = roundtf(v1.x); v1.y = roundtf(v1.y);
                *(float2*)(C + (size_t)r0 * ldc + c0)       = v0;
                *(float2*)(C + (size_t)(r0 + 8) * ldc + c0) = v1;
            } else {
                C[(size_t)(c0    ) * ldc + r0    ] = roundtf(v0.x);
                C[(size_t)(c0 + 1) * ldc + r0    ] = roundtf(v0.y);
                C[(size_t)(c0    ) * ldc + r0 + 8] = roundtf(v1.x);
                C[(size_t)(c0 + 1) * ldc + r0 + 8] = roundtf(v1.y);
            }
        }
    }
}

// Plain z-batched GEMM (logits).
__global__ __launch_bounds__(256, 2) void mma_gemm(
    const float* __restrict__ A, int lda, long zA,
    const float* __restrict__ B, int ldb, long zB,
    float* __restrict__ C, int ldc, long zC,
    const float* __restrict__ bias, long zBias,
    float alpha, int K, int writeMode)
{
    A += (long)blockIdx.z * zA;
    B += (long)blockIdx.z * zB;
    C += (long)blockIdx.z * zC;
    if (bias) bias += (long)blockIdx.z * zBias;
    gemm_tile_body(A, lda, B, ldb, C, ldc, bias, alpha, K,
                   blockIdx.y * 128, blockIdx.x * 128, writeMode);
}

// Split-K GEMM: blockIdx.z = batch*2 + sk. Each split computes Khalf;
// A/B advance by sk*skA / sk*skB (k offsets), C goes to partial sk*skC.
// Bias applied only on split 0.
__global__ __launch_bounds__(256, 2) void mma_gemm_sk(
    const float* __restrict__ A, int lda, long zA, long skA,
    const float* __restrict__ B, int ldb, long zB, long skB,
    float* __restrict__ C, int ldc, long zC, long skC,
    const float* __restrict__ bias,
    float alpha, int Khalf, int writeMode)
{
    const int batch = blockIdx.z >> 1;
    const int sk    = blockIdx.z & 1;
    A += (long)batch * zA + (long)sk * skA;
    B += (long)batch * zB + (long)sk * skB;
    C += (long)batch * zC + (long)sk * skC;
    const float* b = (sk == 0) ? bias : nullptr;
    gemm_tile_body(A, lda, B, ldb, C, ldc, b, alpha, Khalf,
                   blockIdx.y * 128, blockIdx.x * 128, writeMode);
}

// Dense projection launch: 128 Q tiles, 24 K tiles, 24 V tiles = 176 CTAs.
__global__ __launch_bounds__(256, 2) void proj3_gemm(
    const float* __restrict__ tn, const float* __restrict__ vn,
    const float* __restrict__ Wq, const float* __restrict__ Wk,
    const float* __restrict__ Wv,
    const float* __restrict__ bq, const float* __restrict__ bk,
    const float* __restrict__ bv,
    float* __restrict__ q, float* __restrict__ k, float* __restrict__ vt)
{
    const int idx = blockIdx.x;
    int z, local;
    if (idx < 128)      { z = 0; local = idx; }
    else if (idx < 152) { z = 1; local = idx - 128; }
    else                { z = 2; local = idx - 152; }
    const int bn = (local & 3) * 128;
    const int bm = (local >> 2) * 128;
    const float* A = (z == 0) ? tn : vn;
    const float* B = (z == 0) ? Wq : (z == 1) ? Wk : Wv;
    const float* bias = (z == 0) ? bq : (z == 1) ? bk : bv;
    if (z == 2) {
        gemm_tile_body(A, EMBED, B, EMBED, vt, VTOK, bias, 1.0f, EMBED,
                       bm, bn, 2);
    } else {
        float* C = (z == 0) ? q : k;
        gemm_tile_body(A, EMBED, B, EMBED, C, EMBED, bias, 1.0f, EMBED,
                       bm, bn, 1);
    }
}

// ---------------------------------------------------------------------------
__global__ __launch_bounds__(256) void roundw_kernel(
    const float* __restrict__ w0, const float* __restrict__ w1,
    const float* __restrict__ w2, const float* __restrict__ w3,
    const float* __restrict__ w4,
    float* __restrict__ o0, float* __restrict__ o1,
    float* __restrict__ o2, float* __restrict__ o3,
    float* __restrict__ o4)
{
    const int i = blockIdx.x * 256 + threadIdx.x;
    const int z = blockIdx.y;
    const float* w = (z == 0) ? w0 : (z == 1) ? w1 : (z == 2) ? w2
                   : (z == 3) ? w3 : w4;
    float* o = (z == 0) ? o0 : (z == 1) ? o1 : (z == 2) ? o2
             : (z == 3) ? o3 : o4;
    float4 x = *(const float4*)(w + i * 4);
    float4 y;
    y.x = roundtf(x.x); y.y = roundtf(x.y);
    y.z = roundtf(x.z); y.w = roundtf(x.w);
    *(float4*)(o + i * 4) = y;
}

// Sum two partials and round to tf32: out = roundtf(a0 + a1).
__global__ __launch_bounds__(256) void sumround_kernel(
    const float* __restrict__ a0, const float* __restrict__ a1,
    float* __restrict__ out)
{
    const int i = blockIdx.x * 256 + threadIdx.x;
    float4 x = *(const float4*)(a0 + i * 4);
    float4 y = *(const float4*)(a1 + i * 4);
    float4 r;
    r.x = roundtf(x.x + y.x); r.y = roundtf(x.y + y.y);
    r.z = roundtf(x.z + y.z); r.w = roundtf(x.w + y.w);
    *(float4*)(out + i * 4) = r;
}

// ---------------------------------------------------------------------------
// LayerNorm of (x + addx + addx2). round_main rounds primary out; out_r =
// extra tf32-rounded copy.
// ---------------------------------------------------------------------------
__global__ __launch_bounds__(128) void ln_kernel(
    const float* __restrict__ x, const float* __restrict__ addx,
    const float* __restrict__ addx2,
    const float* __restrict__ g, const float* __restrict__ b,
    float* __restrict__ out, float* __restrict__ out_r, int round_main)
{
    const int row = blockIdx.x;
    const int t = threadIdx.x;
    const size_t base = (size_t)row * EMBED;

    float v[4];
#pragma unroll
    for (int i = 0; i < 4; i++) {
        const int c = t + i * 128;
        float val = x[base + c];
        if (addx)  val += addx[base + c];
        if (addx2) val += addx2[base + c];
        v[i] = val;
    }
    float s  = v[0] + v[1] + v[2] + v[3];
    float s2 = v[0]*v[0] + v[1]*v[1] + v[2]*v[2] + v[3]*v[3];
#pragma unroll
    for (int o = 16; o > 0; o >>= 1) {
        s  += __shfl_xor_sync(0xffffffffu, s,  o);
        s2 += __shfl_xor_sync(0xffffffffu, s2, o);
    }
    __shared__ float ss[4], ss2[4];
    const int w = t >> 5, l = t & 31;
    if (l == 0) { ss[w] = s; ss2[w] = s2; }
    __syncthreads();
    s  = ss[0] + ss[1] + ss[2] + ss[3];
    s2 = ss2[0] + ss2[1] + ss2[2] + ss2[3];

    const float mu   = s * (1.0f / EMBED);
    const float var  = s2 * (1.0f / EMBED) - mu * mu;
    const float rstd = rsqrtf(var + 1e-5f);
#pragma unroll
    for (int i = 0; i < 4; i++) {
        const int c = t + i * 128;
        float y = (v[i] - mu) * rstd * g[c] + b[c];
        out[base + c] = round_main ? roundtf(y) : y;
        if (out_r) out_r[base + c] = roundtf(y);
    }
}

// ---------------------------------------------------------------------------
__global__ __launch_bounds__(256) void softmax_kernel(float* __restrict__ S, int ngroups)
{
    const int g = blockIdx.x * blockDim.x + threadIdx.x;
    if (g >= ngroups) return;
    float* p = S + (size_t)g * FR;
    float v[FR];
    float m = -3.0e38f;
#pragma unroll
    for (int i = 0; i < FR; i++) { v[i] = p[i]; m = fmaxf(m, v[i]); }
    float sum = 0.0f;
#pragma unroll
    for (int i = 0; i < FR; i++) { v[i] = __expf(v[i] - m); sum += v[i]; }
    const float inv = 1.0f / sum;
#pragma unroll
    for (int i = 0; i < FR; i++) p[i] = roundtf(v[i] * inv);
}

// ---------------------------------------------------------------------------
extern "C" void kernel_launch(void* const* d_in, const int* in_sizes, int n_in,
                              void* d_out, int out_size)
{
    const float* text  = (const float*)d_in[0];
    const float* video = (const float*)d_in[1];
    const float* ln1_g = (const float*)d_in[2];
    const float* ln1_b = (const float*)d_in[3];
    const float* Wq = (const float*)d_in[4];
    const float* bq = (const float*)d_in[5];
    const float* Wk = (const float*)d_in[6];
    const float* bk = (const float*)d_in[7];
    const float* Wv = (const float*)d_in[8];
    const float* bv = (const float*)d_in[9];
    const float* Wo = (const float*)d_in[10];
    const float* bo = (const float*)d_in[11];
    const float* Wl = (const float*)d_in[12];
    const float* bl = (const float*)d_in[13];
    const float* ln2_g = (const float*)d_in[14];
    const float* ln2_b = (const float*)d_in[15];
    const float* ln3_g = (const float*)d_in[16];
    const float* ln3_b = (const float*)d_in[17];
    float* out = (float*)d_out;

    cudaFuncSetAttribute(mma_gemm,
        cudaFuncAttributeMaxDynamicSharedMemorySize, SMEM_BYTES);
    cudaFuncSetAttribute(mma_gemm_sk,
        cudaFuncAttributeMaxDynamicSharedMemorySize, SMEM_BYTES);
    cudaFuncSetAttribute(proj3_gemm,
        cudaFuncAttributeMaxDynamicSharedMemorySize, SMEM_BYTES);

    float *tn, *vn, *q, *k, *vt, *s, *attn, *attnP, *opreP, *o, *orr, *linP;
    float *wqr, *wkr, *wvr, *wor, *wlr;
    cudaGetSymbolAddress((void**)&tn,    g_tn);
    cudaGetSymbolAddress((void**)&vn,    g_vn);
    cudaGetSymbolAddress((void**)&q,     g_q);
    cudaGetSymbolAddress((void**)&k,     g_k);
    cudaGetSymbolAddress((void**)&vt,    g_vt);
    cudaGetSymbolAddress((void**)&s,     g_s);
    cudaGetSymbolAddress((void**)&attn,  g_attn);
    cudaGetSymbolAddress((void**)&attnP, g_attnP);
    cudaGetSymbolAddress((void**)&opreP, g_opreP);
    cudaGetSymbolAddress((void**)&o,     g_o);
    cudaGetSymbolAddress((void**)&orr,   g_or);
    cudaGetSymbolAddress((void**)&linP,  g_linP);
    cudaGetSymbolAddress((void**)&wqr,   g_wqr);
    cudaGetSymbolAddress((void**)&wkr,   g_wkr);
    cudaGetSymbolAddress((void**)&wvr,   g_wvr);
    cudaGetSymbolAddress((void**)&wor,   g_wor);
    cudaGetSymbolAddress((void**)&wlr,   g_wlr);

    const long NE = (long)TTOK * EMBED;

    // 0) round all weights to tf32 (overlaps LN1)
    roundw_kernel<<<dim3(EMBED*EMBED/1024, 5), 256>>>(
        Wq, Wk, Wv, Wo, Wl, wqr, wkr, wvr, wor, wlr);

    // 1) shared LN1 (outputs tf32-rounded)
    ln_kernel<<<TTOK, 128>>>(text,  nullptr, nullptr, ln1_g, ln1_b, tn, nullptr, 1);
    ln_kernel<<<VTOK, 128>>>(video, nullptr, nullptr, ln1_g, ln1_b, vn, nullptr, 1);

    // 2) Q/K/V projections (V transposed into vt), 176 CTAs
    proj3_gemm<<<176, 256, SMEM_BYTES>>>(
        tn, vn, wqr, wkr, wvr, bq, bk, bv, q, k, vt);

    // 3) logits: S_h = Q_h @ K_h^T / 16 (384 CTAs, 2/SM+)
    mma_gemm<<<dim3(6, 32, 2), 256, SMEM_BYTES>>>(
        q, EMBED, HDIM, k, EMBED, HDIM,
        s, VTOK, (long)TTOK * VTOK, nullptr, 0, 1.0f / 16.0f, HDIM, 0);

    // 4) per-video frame softmax (rounds output)
    softmax_kernel<<<(HEADS * TTOK * NV + 255) / 256, 256>>>(s, HEADS * TTOK * NV);

    // 5) attn split-K: z = head*2+sk, Khalf=384 (256 CTAs)
    mma_gemm_sk<<<dim3(2, 32, 4), 256, SMEM_BYTES>>>(
        s, VTOK, (long)TTOK * VTOK, 384,
        vt, VTOK, (long)HDIM * VTOK, 384,
        attnP, EMBED, HDIM, NE,
        nullptr, 1.0f / 64.0f, 384, 0);
    //    sum partials, round for Wo GEMM
    sumround_kernel<<<TTOK * EMBED / 1024, 256>>>(attnP, attnP + NE, attn);

    // 6) Wo split-K (256 CTAs) + LN2 fusing the partial sum
    mma_gemm_sk<<<dim3(4, 32, 2), 256, SMEM_BYTES>>>(
        attn, EMBED, 0, 256,
        wor, EMBED, 0, 256,
        opreP, EMBED, 0, NE,
        bo, 1.0f, 256, 0);
    ln_kernel<<<TTOK, 128>>>(opreP, opreP + NE, nullptr,
                             ln2_g, ln2_b, o, orr, 0);

    // 7) Wl split-K (256 CTAs) + LN3 fusing residual + both partials
    mma_gemm_sk<<<dim3(4, 32, 2), 256, SMEM_BYTES>>>(
        orr, EMBED, 0, 256,
        wlr, EMBED, 0, 256,
        linP, EMBED, 0, NE,
        bl, 1.0f, 256, 0);
    ln_kernel<<<TTOK, 128>>>(o, linP, linP + NE,
                             ln3_g, ln3_b, out, nullptr, 0);
}

// round 14
// speedup vs baseline: 1.4586x; 1.4586x over previous
#include <cuda_runtime.h>
#include <cuda_fp16.h>
#include <cstdint>

// ---------------------------------------------------------------------------
// XPool cross-modal attention, GB300 round 14: fp16 m16n8k16 GEMM engine.
// Same 11-bit significand as tf32, fp32 accumulate, half the HMMA count and
// half the operand traffic. R12 launch structure (no split-K).
// 128x128 CTA tile, BK=16, 4-stage cp.async, ldmatrix b16 fragments.
// ---------------------------------------------------------------------------

#define EMBED 512
#define HEADS 2
#define HDIM  256
#define TTOK  4096
#define VTOK  768
#define FR    12
#define NV    64

#define APADH  24                      // smem row pitch in halves (48B)
#define STG_H  (128 * APADH)           // halves per stage per matrix (3072)
#define NSTAGE 4
#define SMEM_BYTES (2 * NSTAGE * STG_H * 2)   // 49152

// ------------------------------- scratch ----------------------------------
__device__ __half g_tn  [TTOK*EMBED];
__device__ __half g_vn  [VTOK*EMBED];
__device__ __half g_q   [TTOK*EMBED];
__device__ __half g_k   [VTOK*EMBED];
__device__ __half g_vt  [EMBED*VTOK];         // V transposed [512][768]
__device__ float  g_s   [HEADS*TTOK*VTOK];    // logits (f32)
__device__ __half g_p   [HEADS*TTOK*VTOK];    // softmax probs (half)
__device__ __half g_attn[TTOK*EMBED];
__device__ float  g_opre[TTOK*EMBED];
__device__ float  g_o   [TTOK*EMBED];
__device__ __half g_or  [TTOK*EMBED];         // half copy of o for Wl GEMM
__device__ float  g_lin [TTOK*EMBED];
__device__ __half g_wqr [EMBED*EMBED];
__device__ __half g_wkr [EMBED*EMBED];
__device__ __half g_wvr [EMBED*EMBED];
__device__ __half g_wor [EMBED*EMBED];
__device__ __half g_wlr [EMBED*EMBED];

#define CP16(dst, src) \
    asm volatile("cp.async.cg.shared.global [%0], [%1], 16;" \
        :: "r"(dst), "l"(src) : "memory")
#define CP_COMMIT() asm volatile("cp.async.commit_group;" ::: "memory")
#define CP_WAIT2()  asm volatile("cp.async.wait_group 2;" ::: "memory")
#define CP_WAIT0()  asm volatile("cp.async.wait_group 0;" ::: "memory")

__device__ __forceinline__ void ldsm4(uint32_t& r0, uint32_t& r1,
                                      uint32_t& r2, uint32_t& r3,
                                      uint32_t addr) {
    asm volatile("ldmatrix.sync.aligned.m8n8.x4.shared.b16 {%0,%1,%2,%3}, [%4];"
        : "=r"(r0), "=r"(r1), "=r"(r2), "=r"(r3) : "r"(addr));
}

// ---------------------------------------------------------------------------
// 128x128 NT fp16 GEMM (fp32 accumulate). A,B half. writeMode:
// 0 = f32 C[i,j]; 1 = half C[i,j]; 2 = half transposed C[j][i].
// ---------------------------------------------------------------------------
__device__ __forceinline__ void gemm_tile_body(
    const __half* __restrict__ A, int lda,
    const __half* __restrict__ B, int ldb,
    float* __restrict__ Cf, __half* __restrict__ Ch, int ldc,
    const float* __restrict__ bias,
    float alpha, int K, int bm, int bn, int writeMode)
{
    extern __shared__ __half smh[];
    __half* Asw = smh;                        // [NSTAGE][128][APADH]
    __half* Bsw = smh + NSTAGE * STG_H;

    const int tid  = threadIdx.x;
    const int lane = tid & 31;
    const int warp = tid >> 5;
    const int wm   = (warp >> 1) * 32;
    const int wn   = (warp & 1) * 64;
    const int gid  = lane >> 2;
    const int tig  = lane & 3;

    // producer: 2 threads per row, one 16B chunk (8 halves) each per matrix
    const int prow = tid & 127;
    const int pkc  = (tid >> 7) * 8;          // halves
    const __half* Ap = A + (size_t)(bm + prow) * lda + pkc;
    const __half* Bp = B + (size_t)(bn + prow) * ldb + pkc;

    const uint32_t aBase = (uint32_t)__cvta_generic_to_shared(Asw)
                         + (uint32_t)(prow * APADH + pkc) * 2u;
    const uint32_t bBase = (uint32_t)__cvta_generic_to_shared(Bsw)
                         + (uint32_t)(prow * APADH + pkc) * 2u;

    // ldmatrix fragment addresses (b16 native).
    // lanes 0-7: rows 0-7 k0-7 | 8-15: rows 8-15 k0-7 | 16-23: rows 0-7 k8-15
    // | 24-31: rows 8-15 k8-15
    const int fRow = (lane & 7) + ((lane >> 3) & 1) * 8;
    const int fKh  = ((lane >> 4) & 1) * 8;   // halves
    const uint32_t aFragBase = (uint32_t)__cvta_generic_to_shared(Asw)
        + (uint32_t)((wm + fRow) * APADH + fKh) * 2u;
    const uint32_t bFragBase = (uint32_t)__cvta_generic_to_shared(Bsw)
        + (uint32_t)((wn + fRow) * APADH + fKh) * 2u;

    float acc[2][8][4];
#pragma unroll
    for (int mi = 0; mi < 2; mi++)
#pragma unroll
        for (int ni = 0; ni < 8; ni++)
#pragma unroll
            for (int r = 0; r < 4; r++) acc[mi][ni][r] = 0.0f;

    const int nsteps = K / 16;

#pragma unroll
    for (int s = 0; s < NSTAGE - 1; s++) {
        CP16(aBase + (uint32_t)(s * STG_H) * 2u, Ap + s * 16);
        CP16(bBase + (uint32_t)(s * STG_H) * 2u, Bp + s * 16);
        CP_COMMIT();
    }

#pragma unroll 1
    for (int step = 0; step < nsteps; step++) {
        const int cur = step & (NSTAGE - 1);
        CP_WAIT2();
        __syncthreads();

        const uint32_t aF = aFragBase + (uint32_t)(cur * STG_H) * 2u;
        const uint32_t bF = bFragBase + (uint32_t)(cur * STG_H) * 2u;

        // A fragments: one x4 per mi (16x16 halves)
        uint32_t af[2][4];
#pragma unroll
        for (int mi = 0; mi < 2; mi++)
            ldsm4(af[mi][0], af[mi][1], af[mi][2], af[mi][3],
                  aF + (uint32_t)(mi * 16 * APADH) * 2u);
        // B fragments: one x4 covers two n8 groups
        uint32_t bf[8][2];
#pragma unroll
        for (int j = 0; j < 4; j++)
            ldsm4(bf[2*j][0], bf[2*j+1][0], bf[2*j][1], bf[2*j+1][1],
                  bF + (uint32_t)(j * 16 * APADH) * 2u);

#pragma unroll
        for (int mi = 0; mi < 2; mi++)
#pragma unroll
            for (int ni = 0; ni < 8; ni++) {
                asm("mma.sync.aligned.m16n8k16.row.col.f32.f16.f16.f32 "
                    "{%0,%1,%2,%3}, {%4,%5,%6,%7}, {%8,%9}, {%0,%1,%2,%3};"
                    : "+f"(acc[mi][ni][0]), "+f"(acc[mi][ni][1]),
                      "+f"(acc[mi][ni][2]), "+f"(acc[mi][ni][3])
                    : "r"(af[mi][0]), "r"(af[mi][1]),
                      "r"(af[mi][2]), "r"(af[mi][3]),
                      "r"(bf[ni][0]), "r"(bf[ni][1]));
            }

        const int pf = step + NSTAGE - 1;
        if (pf < nsteps) {
            const int ps = pf & (NSTAGE - 1);
            CP16(aBase + (uint32_t)(ps * STG_H) * 2u, Ap + pf * 16);
            CP16(bBase + (uint32_t)(ps * STG_H) * 2u, Bp + pf * 16);
        }
        CP_COMMIT();
    }
    CP_WAIT0();

    // epilogue
#pragma unroll
    for (int mi = 0; mi < 2; mi++) {
        const int r0 = bm + wm + mi * 16 + gid;
#pragma unroll
        for (int ni = 0; ni < 8; ni++) {
            const int c0 = bn + wn + ni * 8 + tig * 2;
            float bx = 0.0f, by = 0.0f;
            if (bias) { bx = bias[c0]; by = bias[c0 + 1]; }
            float2 v0, v1;
            v0.x = alpha * acc[mi][ni][0] + bx;
            v0.y = alpha * acc[mi][ni][1] + by;
            v1.x = alpha * acc[mi][ni][2] + bx;
            v1.y = alpha * acc[mi][ni][3] + by;
            if (writeMode == 0) {
                *(float2*)(Cf + (size_t)r0 * ldc + c0)       = v0;
                *(float2*)(Cf + (size_t)(r0 + 8) * ldc + c0) = v1;
            } else if (writeMode == 1) {
                *(__half2*)(Ch + (size_t)r0 * ldc + c0) =
                    __floats2half2_rn(v0.x, v0.y);
                *(__half2*)(Ch + (size_t)(r0 + 8) * ldc + c0) =
                    __floats2half2_rn(v1.x, v1.y);
            } else {
                Ch[(size_t)(c0    ) * ldc + r0    ] = __float2half_rn(v0.x);
                Ch[(size_t)(c0 + 1) * ldc + r0    ] = __float2half_rn(v0.y);
                Ch[(size_t)(c0    ) * ldc + r0 + 8] = __float2half_rn(v1.x);
                Ch[(size_t)(c0 + 1) * ldc + r0 + 8] = __float2half_rn(v1.y);
            }
        }
    }
}

// z-batched GEMM (strides in elements of respective types).
__global__ __launch_bounds__(256, 2) void mma_gemm(
    const __half* __restrict__ A, int lda, long zA,
    const __half* __restrict__ B, int ldb, long zB,
    float* __restrict__ Cf, __half* __restrict__ Ch, int ldc, long zC,
    const float* __restrict__ bias, long zBias,
    float alpha, int K, int writeMode)
{
    A += (long)blockIdx.z * zA;
    B += (long)blockIdx.z * zB;
    if (Cf) Cf += (long)blockIdx.z * zC;
    if (Ch) Ch += (long)blockIdx.z * zC;
    if (bias) bias += (long)blockIdx.z * zBias;
    gemm_tile_body(A, lda, B, ldb, Cf, Ch, ldc, bias, alpha, K,
                   blockIdx.y * 128, blockIdx.x * 128, writeMode);
}

// Dense projection launch: 128 Q + 24 K + 24 V tiles = 176 CTAs.
// Q,K half normal; V half TRANSPOSED into vt[512][768].
__global__ __launch_bounds__(256, 2) void proj3_gemm(
    const __half* __restrict__ tn, const __half* __restrict__ vn,
    const __half* __restrict__ Wq, const __half* __restrict__ Wk,
    const __half* __restrict__ Wv,
    const float* __restrict__ bq, const float* __restrict__ bk,
    const float* __restrict__ bv,
    __half* __restrict__ q, __half* __restrict__ k, __half* __restrict__ vt)
{
    const int idx = blockIdx.x;
    int z, local;
    if (idx < 128)      { z = 0; local = idx; }
    else if (idx < 152) { z = 1; local = idx - 128; }
    else                { z = 2; local = idx - 152; }
    const int bn = (local & 3) * 128;
    const int bm = (local >> 2) * 128;
    const __half* A = (z == 0) ? tn : vn;
    const __half* B = (z == 0) ? Wq : (z == 1) ? Wk : Wv;
    const float* bias = (z == 0) ? bq : (z == 1) ? bk : bv;
    if (z == 2) {
        gemm_tile_body(A, EMBED, B, EMBED, nullptr, vt, VTOK, bias, 1.0f,
                       EMBED, bm, bn, 2);
    } else {
        __half* C = (z == 0) ? q : k;
        gemm_tile_body(A, EMBED, B, EMBED, nullptr, C, EMBED, bias, 1.0f,
                       EMBED, bm, bn, 1);
    }
}

// ---------------------------------------------------------------------------
// Round 5 weight matrices to fp16 (one shot, overlaps LN1).
// ---------------------------------------------------------------------------
__global__ __launch_bounds__(256) void roundw_kernel(
    const float* __restrict__ w0, const float* __restrict__ w1,
    const float* __restrict__ w2, const float* __restrict__ w3,
    const float* __restrict__ w4,
    __half* __restrict__ o0, __half* __restrict__ o1,
    __half* __restrict__ o2, __half* __restrict__ o3,
    __half* __restrict__ o4)
{
    const int i = blockIdx.x * 256 + threadIdx.x;
    const int z = blockIdx.y;
    const float* w = (z == 0) ? w0 : (z == 1) ? w1 : (z == 2) ? w2
                   : (z == 3) ? w3 : w4;
    __half* o = (z == 0) ? o0 : (z == 1) ? o1 : (z == 2) ? o2
              : (z == 3) ? o3 : o4;
    float4 x = *(const float4*)(w + i * 4);
    __half2 lo = __floats2half2_rn(x.x, x.y);
    __half2 hi = __floats2half2_rn(x.z, x.w);
    *(__half2*)(o + i * 4)     = lo;
    *(__half2*)(o + i * 4 + 2) = hi;
}

// ---------------------------------------------------------------------------
// LayerNorm of (x + addx). Writes f32 outf (if non-null) and/or half outh.
// ---------------------------------------------------------------------------
__global__ __launch_bounds__(128) void ln_kernel(
    const float* __restrict__ x, const float* __restrict__ addx,
    const float* __restrict__ g, const float* __restrict__ b,
    float* __restrict__ outf, __half* __restrict__ outh)
{
    const int row = blockIdx.x;
    const int t = threadIdx.x;
    const size_t base = (size_t)row * EMBED;

    float v[4];
#pragma unroll
    for (int i = 0; i < 4; i++) {
        const int c = t + i * 128;
        float val = x[base + c];
        if (addx) val += addx[base + c];
        v[i] = val;
    }
    float s  = v[0] + v[1] + v[2] + v[3];
    float s2 = v[0]*v[0] + v[1]*v[1] + v[2]*v[2] + v[3]*v[3];
#pragma unroll
    for (int o = 16; o > 0; o >>= 1) {
        s  += __shfl_xor_sync(0xffffffffu, s,  o);
        s2 += __shfl_xor_sync(0xffffffffu, s2, o);
    }
    __shared__ float ss[4], ss2[4];
    const int w = t >> 5, l = t & 31;
    if (l == 0) { ss[w] = s; ss2[w] = s2; }
    __syncthreads();
    s  = ss[0] + ss[1] + ss[2] + ss[3];
    s2 = ss2[0] + ss2[1] + ss2[2] + ss2[3];

    const float mu   = s * (1.0f / EMBED);
    const float var  = s2 * (1.0f / EMBED) - mu * mu;
    const float rstd = rsqrtf(var + 1e-5f);
#pragma unroll
    for (int i = 0; i < 4; i++) {
        const int c = t + i * 128;
        float y = (v[i] - mu) * rstd * g[c] + b[c];
        if (outf) outf[base + c] = y;
        if (outh) outh[base + c] = __float2half_rn(y);
    }
}

// ---------------------------------------------------------------------------
// Per-(video,head,token) softmax over 12 frames; f32 in, half out.
// ---------------------------------------------------------------------------
__global__ __launch_bounds__(256) void softmax_kernel(
    const float* __restrict__ S, __half* __restrict__ P, int ngroups)
{
    const int g = blockIdx.x * blockDim.x + threadIdx.x;
    if (g >= ngroups) return;
    const float* p = S + (size_t)g * FR;
    __half* q = P + (size_t)g * FR;
    float v[FR];
    float m = -3.0e38f;
#pragma unroll
    for (int i = 0; i < FR; i++) { v[i] = p[i]; m = fmaxf(m, v[i]); }
    float sum = 0.0f;
#pragma unroll
    for (int i = 0; i < FR; i++) { v[i] = __expf(v[i] - m); sum += v[i]; }
    const float inv = 1.0f / sum;
#pragma unroll
    for (int i = 0; i < FR; i++) q[i] = __float2half_rn(v[i] * inv);
}

// ---------------------------------------------------------------------------
extern "C" void kernel_launch(void* const* d_in, const int* in_sizes, int n_in,
                              void* d_out, int out_size)
{
    const float* text  = (const float*)d_in[0];
    const float* video = (const float*)d_in[1];
    const float* ln1_g = (const float*)d_in[2];
    const float* ln1_b = (const float*)d_in[3];
    const float* Wq = (const float*)d_in[4];
    const float* bq = (const float*)d_in[5];
    const float* Wk = (const float*)d_in[6];
    const float* bk = (const float*)d_in[7];
    const float* Wv = (const float*)d_in[8];
    const float* bv = (const float*)d_in[9];
    const float* Wo = (const float*)d_in[10];
    const float* bo = (const float*)d_in[11];
    const float* Wl = (const float*)d_in[12];
    const float* bl = (const float*)d_in[13];
    const float* ln2_g = (const float*)d_in[14];
    const float* ln2_b = (const float*)d_in[15];
    const float* ln3_g = (const float*)d_in[16];
    const float* ln3_b = (const float*)d_in[17];
    float* out = (float*)d_out;

    cudaFuncSetAttribute(mma_gemm,
        cudaFuncAttributeMaxDynamicSharedMemorySize, SMEM_BYTES);
    cudaFuncSetAttribute(proj3_gemm,
        cudaFuncAttributeMaxDynamicSharedMemorySize, SMEM_BYTES);

    __half *tn, *vn, *q, *k, *vt, *p, *attn, *orr;
    __half *wqr, *wkr, *wvr, *wor, *wlr;
    float *s, *opre, *o, *lin;
    cudaGetSymbolAddress((void**)&tn,   g_tn);
    cudaGetSymbolAddress((void**)&vn,   g_vn);
    cudaGetSymbolAddress((void**)&q,    g_q);
    cudaGetSymbolAddress((void**)&k,    g_k);
    cudaGetSymbolAddress((void**)&vt,   g_vt);
    cudaGetSymbolAddress((void**)&s,    g_s);
    cudaGetSymbolAddress((void**)&p,    g_p);
    cudaGetSymbolAddress((void**)&attn, g_attn);
    cudaGetSymbolAddress((void**)&opre, g_opre);
    cudaGetSymbolAddress((void**)&o,    g_o);
    cudaGetSymbolAddress((void**)&orr,  g_or);
    cudaGetSymbolAddress((void**)&lin,  g_lin);
    cudaGetSymbolAddress((void**)&wqr,  g_wqr);
    cudaGetSymbolAddress((void**)&wkr,  g_wkr);
    cudaGetSymbolAddress((void**)&wvr,  g_wvr);
    cudaGetSymbolAddress((void**)&wor,  g_wor);
    cudaGetSymbolAddress((void**)&wlr,  g_wlr);

    // 0) round weights to fp16 (overlaps LN1)
    roundw_kernel<<<dim3(EMBED*EMBED/1024, 5), 256>>>(
        Wq, Wk, Wv, Wo, Wl, wqr, wkr, wvr, wor, wlr);

    // 1) shared LN1 -> half
    ln_kernel<<<TTOK, 128>>>(text,  nullptr, ln1_g, ln1_b, nullptr, tn);
    ln_kernel<<<VTOK, 128>>>(video, nullptr, ln1_g, ln1_b, nullptr, vn);

    // 2) Q/K/V projections (V transposed into vt), 176 CTAs
    proj3_gemm<<<176, 256, SMEM_BYTES>>>(
        tn, vn, wqr, wkr, wvr, bq, bk, bv, q, k, vt);

    // 3) logits: S_h = Q_h @ K_h^T / 16 -> f32 s (384 CTAs)
    mma_gemm<<<dim3(6, 32, 2), 256, SMEM_BYTES>>>(
        q, EMBED, HDIM, k, EMBED, HDIM,
        s, nullptr, VTOK, (long)TTOK * VTOK, nullptr, 0,
        1.0f / 16.0f, HDIM, 0);

    // 4) per-video frame softmax -> half p
    softmax_kernel<<<(HEADS * TTOK * NV + 255) / 256, 256>>>(
        s, p, HEADS * TTOK * NV);

    // 5) attn_h = P_h @ V_h / 64 -> half attn (128 CTAs)
    mma_gemm<<<dim3(2, 32, 2), 256, SMEM_BYTES>>>(
        p, VTOK, (long)TTOK * VTOK, vt, VTOK, (long)HDIM * VTOK,
        nullptr, attn, EMBED, HDIM, nullptr, 0,
        1.0f / 64.0f, VTOK, 1);

    // 6) output projection -> f32 opre; LN2 -> o (f32) + orr (half)
    mma_gemm<<<dim3(4, 32, 1), 256, SMEM_BYTES>>>(
        attn, EMBED, 0, wor, EMBED, 0,
        opre, nullptr, EMBED, 0, bo, 0, 1.0f, EMBED, 0);
    ln_kernel<<<TTOK, 128>>>(opre, nullptr, ln2_g, ln2_b, o, orr);

    // 7) linear -> f32 lin; LN3(o + lin) -> out
    mma_gemm<<<dim3(4, 32, 1), 256, SMEM_BYTES>>>(
        orr, EMBED, 0, wlr, EMBED, 0,
        lin, nullptr, EMBED, 0, bl, 0, 1.0f, EMBED, 0);
    ln_kernel<<<TTOK, 128>>>(o, lin, ln3_g, ln3_b, out, nullptr);
}

// round 15
// speedup vs baseline: 1.4870x; 1.0195x over previous
#include <cuda_runtime.h>
#include <cuda_fp16.h>
#include <cstdint>

// ---------------------------------------------------------------------------
// XPool cross-modal attention, GB300 round 15: fp16 m16n8k16 engine,
// BK=32 per pipeline stage (half the syncs), 3-stage cp.async, 2 CTAs/SM.
// All pre-GEMM prep (LN1 x2 + 5 weight roundings) fused into one launch.
// ---------------------------------------------------------------------------

#define EMBED 512
#define HEADS 2
#define HDIM  256
#define TTOK  4096
#define VTOK  768
#define FR    12
#define NV    64

#define APADH  40                      // smem row pitch in halves (80B)
#define STG_H  (128 * APADH)           // halves per stage per matrix (5120)
#define NSTAGE 3
#define SMEM_BYTES (2 * NSTAGE * STG_H * 2)   // 61440

// ------------------------------- scratch ----------------------------------
__device__ __half g_tn  [TTOK*EMBED];
__device__ __half g_vn  [VTOK*EMBED];
__device__ __half g_q   [TTOK*EMBED];
__device__ __half g_k   [VTOK*EMBED];
__device__ __half g_vt  [EMBED*VTOK];
__device__ float  g_s   [HEADS*TTOK*VTOK];
__device__ __half g_p   [HEADS*TTOK*VTOK];
__device__ __half g_attn[TTOK*EMBED];
__device__ float  g_opre[TTOK*EMBED];
__device__ float  g_o   [TTOK*EMBED];
__device__ __half g_or  [TTOK*EMBED];
__device__ float  g_lin [TTOK*EMBED];
__device__ __half g_wqr [EMBED*EMBED];
__device__ __half g_wkr [EMBED*EMBED];
__device__ __half g_wvr [EMBED*EMBED];
__device__ __half g_wor [EMBED*EMBED];
__device__ __half g_wlr [EMBED*EMBED];

#define CP16(dst, src) \
    asm volatile("cp.async.cg.shared.global [%0], [%1], 16;" \
        :: "r"(dst), "l"(src) : "memory")
#define CP_COMMIT() asm volatile("cp.async.commit_group;" ::: "memory")
#define CP_WAIT1()  asm volatile("cp.async.wait_group 1;" ::: "memory")
#define CP_WAIT0()  asm volatile("cp.async.wait_group 0;" ::: "memory")

__device__ __forceinline__ void ldsm4(uint32_t& r0, uint32_t& r1,
                                      uint32_t& r2, uint32_t& r3,
                                      uint32_t addr) {
    asm volatile("ldmatrix.sync.aligned.m8n8.x4.shared.b16 {%0,%1,%2,%3}, [%4];"
        : "=r"(r0), "=r"(r1), "=r"(r2), "=r"(r3) : "r"(addr));
}

// ---------------------------------------------------------------------------
// 128x128 NT fp16 GEMM (fp32 accumulate), BK=32, 3-stage.
// writeMode: 0 = f32 C; 1 = half C; 2 = half transposed C[j][i].
// ---------------------------------------------------------------------------
__device__ __forceinline__ void gemm_tile_body(
    const __half* __restrict__ A, int lda,
    const __half* __restrict__ B, int ldb,
    float* __restrict__ Cf, __half* __restrict__ Ch, int ldc,
    const float* __restrict__ bias,
    float alpha, int K, int bm, int bn, int writeMode)
{
    extern __shared__ __half smh[];
    __half* Asw = smh;                        // [NSTAGE][128][APADH]
    __half* Bsw = smh + NSTAGE * STG_H;

    const int tid  = threadIdx.x;
    const int lane = tid & 31;
    const int warp = tid >> 5;
    const int wm   = (warp >> 1) * 32;
    const int wn   = (warp & 1) * 64;
    const int gid  = lane >> 2;
    const int tig  = lane & 3;

    // producer: 2 threads per row, each 16 halves (2x CP16) per matrix
    const int prow = tid & 127;
    const int pkc  = (tid >> 7) * 16;         // halves
    const __half* Ap = A + (size_t)(bm + prow) * lda + pkc;
    const __half* Bp = B + (size_t)(bn + prow) * ldb + pkc;

    const uint32_t aBase = (uint32_t)__cvta_generic_to_shared(Asw)
                         + (uint32_t)(prow * APADH + pkc) * 2u;
    const uint32_t bBase = (uint32_t)__cvta_generic_to_shared(Bsw)
                         + (uint32_t)(prow * APADH + pkc) * 2u;

    // ldmatrix fragment addresses within a k16 window
    const int fRow = (lane & 7) + ((lane >> 3) & 1) * 8;
    const int fKh  = ((lane >> 4) & 1) * 8;
    const uint32_t aFragBase = (uint32_t)__cvta_generic_to_shared(Asw)
        + (uint32_t)((wm + fRow) * APADH + fKh) * 2u;
    const uint32_t bFragBase = (uint32_t)__cvta_generic_to_shared(Bsw)
        + (uint32_t)((wn + fRow) * APADH + fKh) * 2u;

    float acc[2][8][4];
#pragma unroll
    for (int mi = 0; mi < 2; mi++)
#pragma unroll
        for (int ni = 0; ni < 8; ni++)
#pragma unroll
            for (int r = 0; r < 4; r++) acc[mi][ni][r] = 0.0f;

    const int nsteps = K / 32;

#pragma unroll
    for (int s = 0; s < NSTAGE - 1; s++) {
        const uint32_t ao = aBase + (uint32_t)(s * STG_H) * 2u;
        const uint32_t bo = bBase + (uint32_t)(s * STG_H) * 2u;
        CP16(ao,      Ap + s * 32);
        CP16(ao + 16, Ap + s * 32 + 8);
        CP16(bo,      Bp + s * 32);
        CP16(bo + 16, Bp + s * 32 + 8);
        CP_COMMIT();
    }

    int cur = 0;
#pragma unroll 1
    for (int step = 0; step < nsteps; step++) {
        CP_WAIT1();
        __syncthreads();

        const uint32_t aF = aFragBase + (uint32_t)(cur * STG_H) * 2u;
        const uint32_t bF = bFragBase + (uint32_t)(cur * STG_H) * 2u;

#pragma unroll
        for (int kk = 0; kk < 2; kk++) {
            const uint32_t kOff = (uint32_t)(kk * 16) * 2u;
            uint32_t af[2][4];
#pragma unroll
            for (int mi = 0; mi < 2; mi++)
                ldsm4(af[mi][0], af[mi][1], af[mi][2], af[mi][3],
                      aF + kOff + (uint32_t)(mi * 16 * APADH) * 2u);
            uint32_t bf[8][2];
#pragma unroll
            for (int j = 0; j < 4; j++)
                ldsm4(bf[2*j][0], bf[2*j+1][0], bf[2*j][1], bf[2*j+1][1],
                      bF + kOff + (uint32_t)(j * 16 * APADH) * 2u);
#pragma unroll
            for (int mi = 0; mi < 2; mi++)
#pragma unroll
                for (int ni = 0; ni < 8; ni++) {
                    asm("mma.sync.aligned.m16n8k16.row.col.f32.f16.f16.f32 "
                        "{%0,%1,%2,%3}, {%4,%5,%6,%7}, {%8,%9}, {%0,%1,%2,%3};"
                        : "+f"(acc[mi][ni][0]), "+f"(acc[mi][ni][1]),
                          "+f"(acc[mi][ni][2]), "+f"(acc[mi][ni][3])
                        : "r"(af[mi][0]), "r"(af[mi][1]),
                          "r"(af[mi][2]), "r"(af[mi][3]),
                          "r"(bf[ni][0]), "r"(bf[ni][1]));
                }
        }

        const int pf = step + NSTAGE - 1;
        if (pf < nsteps) {
            int ps = cur + NSTAGE - 1; if (ps >= NSTAGE) ps -= NSTAGE;
            const uint32_t ao = aBase + (uint32_t)(ps * STG_H) * 2u;
            const uint32_t bo = bBase + (uint32_t)(ps * STG_H) * 2u;
            CP16(ao,      Ap + pf * 32);
            CP16(ao + 16, Ap + pf * 32 + 8);
            CP16(bo,      Bp + pf * 32);
            CP16(bo + 16, Bp + pf * 32 + 8);
        }
        CP_COMMIT();
        cur = (cur + 1 == NSTAGE) ? 0 : cur + 1;
    }
    CP_WAIT0();

    // epilogue
#pragma unroll
    for (int mi = 0; mi < 2; mi++) {
        const int r0 = bm + wm + mi * 16 + gid;
#pragma unroll
        for (int ni = 0; ni < 8; ni++) {
            const int c0 = bn + wn + ni * 8 + tig * 2;
            float bx = 0.0f, by = 0.0f;
            if (bias) { bx = bias[c0]; by = bias[c0 + 1]; }
            float2 v0, v1;
            v0.x = alpha * acc[mi][ni][0] + bx;
            v0.y = alpha * acc[mi][ni][1] + by;
            v1.x = alpha * acc[mi][ni][2] + bx;
            v1.y = alpha * acc[mi][ni][3] + by;
            if (writeMode == 0) {
                *(float2*)(Cf + (size_t)r0 * ldc + c0)       = v0;
                *(float2*)(Cf + (size_t)(r0 + 8) * ldc + c0) = v1;
            } else if (writeMode == 1) {
                *(__half2*)(Ch + (size_t)r0 * ldc + c0) =
                    __floats2half2_rn(v0.x, v0.y);
                *(__half2*)(Ch + (size_t)(r0 + 8) * ldc + c0) =
                    __floats2half2_rn(v1.x, v1.y);
            } else {
                Ch[(size_t)(c0    ) * ldc + r0    ] = __float2half_rn(v0.x);
                Ch[(size_t)(c0 + 1) * ldc + r0    ] = __float2half_rn(v0.y);
                Ch[(size_t)(c0    ) * ldc + r0 + 8] = __float2half_rn(v1.x);
                Ch[(size_t)(c0 + 1) * ldc + r0 + 8] = __float2half_rn(v1.y);
            }
        }
    }
}

__global__ __launch_bounds__(256, 2) void mma_gemm(
    const __half* __restrict__ A, int lda, long zA,
    const __half* __restrict__ B, int ldb, long zB,
    float* __restrict__ Cf, __half* __restrict__ Ch, int ldc, long zC,
    const float* __restrict__ bias, long zBias,
    float alpha, int K, int writeMode)
{
    A += (long)blockIdx.z * zA;
    B += (long)blockIdx.z * zB;
    if (Cf) Cf += (long)blockIdx.z * zC;
    if (Ch) Ch += (long)blockIdx.z * zC;
    if (bias) bias += (long)blockIdx.z * zBias;
    gemm_tile_body(A, lda, B, ldb, Cf, Ch, ldc, bias, alpha, K,
                   blockIdx.y * 128, blockIdx.x * 128, writeMode);
}

// Dense projection launch: 128 Q + 24 K + 24 V tiles = 176 CTAs.
__global__ __launch_bounds__(256, 2) void proj3_gemm(
    const __half* __restrict__ tn, const __half* __restrict__ vn,
    const __half* __restrict__ Wq, const __half* __restrict__ Wk,
    const __half* __restrict__ Wv,
    const float* __restrict__ bq, const float* __restrict__ bk,
    const float* __restrict__ bv,
    __half* __restrict__ q, __half* __restrict__ k, __half* __restrict__ vt)
{
    const int idx = blockIdx.x;
    int z, local;
    if (idx < 128)      { z = 0; local = idx; }
    else if (idx < 152) { z = 1; local = idx - 128; }
    else                { z = 2; local = idx - 152; }
    const int bn = (local & 3) * 128;
    const int bm = (local >> 2) * 128;
    const __half* A = (z == 0) ? tn : vn;
    const __half* B = (z == 0) ? Wq : (z == 1) ? Wk : Wv;
    const float* bias = (z == 0) ? bq : (z == 1) ? bk : bv;
    if (z == 2) {
        gemm_tile_body(A, EMBED, B, EMBED, nullptr, vt, VTOK, bias, 1.0f,
                       EMBED, bm, bn, 2);
    } else {
        __half* C = (z == 0) ? q : k;
        gemm_tile_body(A, EMBED, B, EMBED, nullptr, C, EMBED, bias, 1.0f,
                       EMBED, bm, bn, 1);
    }
}

// ---------------------------------------------------------------------------
// LN row body (shared by prep + ln kernels).
// ---------------------------------------------------------------------------
__device__ __forceinline__ void ln_row(
    const float* __restrict__ x, const float* __restrict__ addx,
    const float* __restrict__ g, const float* __restrict__ b,
    float* __restrict__ outf, __half* __restrict__ outh, int row)
{
    const int t = threadIdx.x;
    const size_t base = (size_t)row * EMBED;

    float v[4];
#pragma unroll
    for (int i = 0; i < 4; i++) {
        const int c = t + i * 128;
        float val = x[base + c];
        if (addx) val += addx[base + c];
        v[i] = val;
    }
    float s  = v[0] + v[1] + v[2] + v[3];
    float s2 = v[0]*v[0] + v[1]*v[1] + v[2]*v[2] + v[3]*v[3];
#pragma unroll
    for (int o = 16; o > 0; o >>= 1) {
        s  += __shfl_xor_sync(0xffffffffu, s,  o);
        s2 += __shfl_xor_sync(0xffffffffu, s2, o);
    }
    __shared__ float ss[4], ss2[4];
    const int w = t >> 5, l = t & 31;
    if (l == 0) { ss[w] = s; ss2[w] = s2; }
    __syncthreads();
    s  = ss[0] + ss[1] + ss[2] + ss[3];
    s2 = ss2[0] + ss2[1] + ss2[2] + ss2[3];

    const float mu   = s * (1.0f / EMBED);
    const float var  = s2 * (1.0f / EMBED) - mu * mu;
    const float rstd = rsqrtf(var + 1e-5f);
#pragma unroll
    for (int i = 0; i < 4; i++) {
        const int c = t + i * 128;
        float y = (v[i] - mu) * rstd * g[c] + b[c];
        if (outf) outf[base + c] = y;
        if (outh) outh[base + c] = __float2half_rn(y);
    }
}

// Prep: blocks [0,TTOK) = LN1 text; [TTOK,TTOK+VTOK) = LN1 video;
// remaining 1280 blocks = fp16 rounding of the 5 weight matrices.
__global__ __launch_bounds__(128) void prep_kernel(
    const float* __restrict__ text, const float* __restrict__ video,
    const float* __restrict__ ln1_g, const float* __restrict__ ln1_b,
    __half* __restrict__ tn, __half* __restrict__ vn,
    const float* __restrict__ w0, const float* __restrict__ w1,
    const float* __restrict__ w2, const float* __restrict__ w3,
    const float* __restrict__ w4,
    __half* __restrict__ o0, __half* __restrict__ o1,
    __half* __restrict__ o2, __half* __restrict__ o3,
    __half* __restrict__ o4)
{
    const int blk = blockIdx.x;
    if (blk < TTOK) {
        ln_row(text, nullptr, ln1_g, ln1_b, nullptr, tn, blk);
    } else if (blk < TTOK + VTOK) {
        ln_row(video, nullptr, ln1_g, ln1_b, nullptr, vn, blk - TTOK);
    } else {
        const int wb = blk - TTOK - VTOK;          // 0..1279
        const int z  = wb >> 8;                    // 256 blocks per weight
        const int i  = (wb & 255) * 128 + threadIdx.x;  // x4 elems
        const float* w = (z == 0) ? w0 : (z == 1) ? w1 : (z == 2) ? w2
                       : (z == 3) ? w3 : w4;
        __half* o = (z == 0) ? o0 : (z == 1) ? o1 : (z == 2) ? o2
                  : (z == 3) ? o3 : o4;
        float4 x = *(const float4*)(w + (size_t)i * 8);
        float4 y = *(const float4*)(w + (size_t)i * 8 + 4);
        *(__half2*)(o + (size_t)i * 8)     = __floats2half2_rn(x.x, x.y);
        *(__half2*)(o + (size_t)i * 8 + 2) = __floats2half2_rn(x.z, x.w);
        *(__half2*)(o + (size_t)i * 8 + 4) = __floats2half2_rn(y.x, y.y);
        *(__half2*)(o + (size_t)i * 8 + 6) = __floats2half2_rn(y.z, y.w);
    }
}

__global__ __launch_bounds__(128) void ln_kernel(
    const float* __restrict__ x, const float* __restrict__ addx,
    const float* __restrict__ g, const float* __restrict__ b,
    float* __restrict__ outf, __half* __restrict__ outh)
{
    ln_row(x, addx, g, b, outf, outh, blockIdx.x);
}

// ---------------------------------------------------------------------------
// Per-(video,head,token) softmax over 12 frames; f32 in, half out.
// ---------------------------------------------------------------------------
__global__ __launch_bounds__(256) void softmax_kernel(
    const float* __restrict__ S, __half* __restrict__ P, int ngroups)
{
    const int g = blockIdx.x * blockDim.x + threadIdx.x;
    if (g >= ngroups) return;
    const float* p = S + (size_t)g * FR;
    __half* q = P + (size_t)g * FR;
    float v[FR];
    float m = -3.0e38f;
#pragma unroll
    for (int i = 0; i < FR; i++) { v[i] = p[i]; m = fmaxf(m, v[i]); }
    float sum = 0.0f;
#pragma unroll
    for (int i = 0; i < FR; i++) { v[i] = __expf(v[i] - m); sum += v[i]; }
    const float inv = 1.0f / sum;
#pragma unroll
    for (int i = 0; i < FR; i++) q[i] = __float2half_rn(v[i] * inv);
}

// ---------------------------------------------------------------------------
extern "C" void kernel_launch(void* const* d_in, const int* in_sizes, int n_in,
                              void* d_out, int out_size)
{
    const float* text  = (const float*)d_in[0];
    const float* video = (const float*)d_in[1];
    const float* ln1_g = (const float*)d_in[2];
    const float* ln1_b = (const float*)d_in[3];
    const float* Wq = (const float*)d_in[4];
    const float* bq = (const float*)d_in[5];
    const float* Wk = (const float*)d_in[6];
    const float* bk = (const float*)d_in[7];
    const float* Wv = (const float*)d_in[8];
    const float* bv = (const float*)d_in[9];
    const float* Wo = (const float*)d_in[10];
    const float* bo = (const float*)d_in[11];
    const float* Wl = (const float*)d_in[12];
    const float* bl = (const float*)d_in[13];
    const float* ln2_g = (const float*)d_in[14];
    const float* ln2_b = (const float*)d_in[15];
    const float* ln3_g = (const float*)d_in[16];
    const float* ln3_b = (const float*)d_in[17];
    float* out = (float*)d_out;

    cudaFuncSetAttribute(mma_gemm,
        cudaFuncAttributeMaxDynamicSharedMemorySize, SMEM_BYTES);
    cudaFuncSetAttribute(proj3_gemm,
        cudaFuncAttributeMaxDynamicSharedMemorySize, SMEM_BYTES);

    __half *tn, *vn, *q, *k, *vt, *p, *attn, *orr;
    __half *wqr, *wkr, *wvr, *wor, *wlr;
    float *s, *opre, *o, *lin;
    cudaGetSymbolAddress((void**)&tn,   g_tn);
    cudaGetSymbolAddress((void**)&vn,   g_vn);
    cudaGetSymbolAddress((void**)&q,    g_q);
    cudaGetSymbolAddress((void**)&k,    g_k);
    cudaGetSymbolAddress((void**)&vt,   g_vt);
    cudaGetSymbolAddress((void**)&s,    g_s);
    cudaGetSymbolAddress((void**)&p,    g_p);
    cudaGetSymbolAddress((void**)&attn, g_attn);
    cudaGetSymbolAddress((void**)&opre, g_opre);
    cudaGetSymbolAddress((void**)&o,    g_o);
    cudaGetSymbolAddress((void**)&orr,  g_or);
    cudaGetSymbolAddress((void**)&lin,  g_lin);
    cudaGetSymbolAddress((void**)&wqr,  g_wqr);
    cudaGetSymbolAddress((void**)&wkr,  g_wkr);
    cudaGetSymbolAddress((void**)&wvr,  g_wvr);
    cudaGetSymbolAddress((void**)&wor,  g_wor);
    cudaGetSymbolAddress((void**)&wlr,  g_wlr);

    // 1) fused prep: LN1 (text+video) + 5 weight roundings
    prep_kernel<<<TTOK + VTOK + 1280, 128>>>(
        text, video, ln1_g, ln1_b, tn, vn,
        Wq, Wk, Wv, Wo, Wl, wqr, wkr, wvr, wor, wlr);

    // 2) Q/K/V projections (V transposed into vt), 176 CTAs
    proj3_gemm<<<176, 256, SMEM_BYTES>>>(
        tn, vn, wqr, wkr, wvr, bq, bk, bv, q, k, vt);

    // 3) logits: S_h = Q_h @ K_h^T / 16 -> f32 s (384 CTAs)
    mma_gemm<<<dim3(6, 32, 2), 256, SMEM_BYTES>>>(
        q, EMBED, HDIM, k, EMBED, HDIM,
        s, nullptr, VTOK, (long)TTOK * VTOK, nullptr, 0,
        1.0f / 16.0f, HDIM, 0);

    // 4) per-video frame softmax -> half p
    softmax_kernel<<<(HEADS * TTOK * NV + 255) / 256, 256>>>(
        s, p, HEADS * TTOK * NV);

    // 5) attn_h = P_h @ V_h / 64 -> half attn (128 CTAs)
    mma_gemm<<<dim3(2, 32, 2), 256, SMEM_BYTES>>>(
        p, VTOK, (long)TTOK * VTOK, vt, VTOK, (long)HDIM * VTOK,
        nullptr, attn, EMBED, HDIM, nullptr, 0,
        1.0f / 64.0f, VTOK, 1);

    // 6) output projection -> f32 opre; LN2 -> o (f32) + orr (half)
    mma_gemm<<<dim3(4, 32, 1), 256, SMEM_BYTES>>>(
        attn, EMBED, 0, wor, EMBED, 0,
        opre, nullptr, EMBED, 0, bo, 0, 1.0f, EMBED, 0);
    ln_kernel<<<TTOK, 128>>>(opre, nullptr, ln2_g, ln2_b, o, orr);

    // 7) linear -> f32 lin; LN3(o + lin) -> out
    mma_gemm<<<dim3(4, 32, 1), 256, SMEM_BYTES>>>(
        orr, EMBED, 0, wlr, EMBED, 0,
        lin, nullptr, EMBED, 0, bl, 0, 1.0f, EMBED, 0);
    ln_kernel<<<TTOK, 128>>>(o, lin, ln3_g, ln3_b, out, nullptr);
}

// round 16
// speedup vs baseline: 1.7432x; 1.1723x over previous
#include <cuda_runtime.h>
#include <cuda_fp16.h>
#include <cstdint>

// ---------------------------------------------------------------------------
// XPool cross-modal attention, GB300 round 16: fp16 m16n8k16 engine (R15) +
// half-precision logits and a coalesced smem-staged softmax.
// ---------------------------------------------------------------------------

#define EMBED 512
#define HEADS 2
#define HDIM  256
#define TTOK  4096
#define VTOK  768
#define FR    12
#define NV    64

#define APADH  40
#define STG_H  (128 * APADH)
#define NSTAGE 3
#define SMEM_BYTES (2 * NSTAGE * STG_H * 2)   // 61440

// ------------------------------- scratch ----------------------------------
__device__ __half g_tn  [TTOK*EMBED];
__device__ __half g_vn  [VTOK*EMBED];
__device__ __half g_q   [TTOK*EMBED];
__device__ __half g_k   [VTOK*EMBED];
__device__ __half g_vt  [EMBED*VTOK];
__device__ __half g_sh  [HEADS*TTOK*VTOK];    // logits (half)
__device__ __half g_p   [HEADS*TTOK*VTOK];    // probs (half)
__device__ __half g_attn[TTOK*EMBED];
__device__ float  g_opre[TTOK*EMBED];
__device__ float  g_o   [TTOK*EMBED];
__device__ __half g_or  [TTOK*EMBED];
__device__ float  g_lin [TTOK*EMBED];
__device__ __half g_wqr [EMBED*EMBED];
__device__ __half g_wkr [EMBED*EMBED];
__device__ __half g_wvr [EMBED*EMBED];
__device__ __half g_wor [EMBED*EMBED];
__device__ __half g_wlr [EMBED*EMBED];

#define CP16(dst, src) \
    asm volatile("cp.async.cg.shared.global [%0], [%1], 16;" \
        :: "r"(dst), "l"(src) : "memory")
#define CP_COMMIT() asm volatile("cp.async.commit_group;" ::: "memory")
#define CP_WAIT1()  asm volatile("cp.async.wait_group 1;" ::: "memory")
#define CP_WAIT0()  asm volatile("cp.async.wait_group 0;" ::: "memory")

__device__ __forceinline__ void ldsm4(uint32_t& r0, uint32_t& r1,
                                      uint32_t& r2, uint32_t& r3,
                                      uint32_t addr) {
    asm volatile("ldmatrix.sync.aligned.m8n8.x4.shared.b16 {%0,%1,%2,%3}, [%4];"
        : "=r"(r0), "=r"(r1), "=r"(r2), "=r"(r3) : "r"(addr));
}

// ---------------------------------------------------------------------------
// 128x128 NT fp16 GEMM (fp32 accumulate), BK=32, 3-stage.
// writeMode: 0 = f32 C; 1 = half C; 2 = half transposed C[j][i].
// ---------------------------------------------------------------------------
__device__ __forceinline__ void gemm_tile_body(
    const __half* __restrict__ A, int lda,
    const __half* __restrict__ B, int ldb,
    float* __restrict__ Cf, __half* __restrict__ Ch, int ldc,
    const float* __restrict__ bias,
    float alpha, int K, int bm, int bn, int writeMode)
{
    extern __shared__ __half smh[];
    __half* Asw = smh;
    __half* Bsw = smh + NSTAGE * STG_H;

    const int tid  = threadIdx.x;
    const int lane = tid & 31;
    const int warp = tid >> 5;
    const int wm   = (warp >> 1) * 32;
    const int wn   = (warp & 1) * 64;
    const int gid  = lane >> 2;
    const int tig  = lane & 3;

    const int prow = tid & 127;
    const int pkc  = (tid >> 7) * 16;
    const __half* Ap = A + (size_t)(bm + prow) * lda + pkc;
    const __half* Bp = B + (size_t)(bn + prow) * ldb + pkc;

    const uint32_t aBase = (uint32_t)__cvta_generic_to_shared(Asw)
                         + (uint32_t)(prow * APADH + pkc) * 2u;
    const uint32_t bBase = (uint32_t)__cvta_generic_to_shared(Bsw)
                         + (uint32_t)(prow * APADH + pkc) * 2u;

    const int fRow = (lane & 7) + ((lane >> 3) & 1) * 8;
    const int fKh  = ((lane >> 4) & 1) * 8;
    const uint32_t aFragBase = (uint32_t)__cvta_generic_to_shared(Asw)
        + (uint32_t)((wm + fRow) * APADH + fKh) * 2u;
    const uint32_t bFragBase = (uint32_t)__cvta_generic_to_shared(Bsw)
        + (uint32_t)((wn + fRow) * APADH + fKh) * 2u;

    float acc[2][8][4];
#pragma unroll
    for (int mi = 0; mi < 2; mi++)
#pragma unroll
        for (int ni = 0; ni < 8; ni++)
#pragma unroll
            for (int r = 0; r < 4; r++) acc[mi][ni][r] = 0.0f;

    const int nsteps = K / 32;

#pragma unroll
    for (int s = 0; s < NSTAGE - 1; s++) {
        const uint32_t ao = aBase + (uint32_t)(s * STG_H) * 2u;
        const uint32_t bo = bBase + (uint32_t)(s * STG_H) * 2u;
        CP16(ao,      Ap + s * 32);
        CP16(ao + 16, Ap + s * 32 + 8);
        CP16(bo,      Bp + s * 32);
        CP16(bo + 16, Bp + s * 32 + 8);
        CP_COMMIT();
    }

    int cur = 0;
#pragma unroll 1
    for (int step = 0; step < nsteps; step++) {
        CP_WAIT1();
        __syncthreads();

        const uint32_t aF = aFragBase + (uint32_t)(cur * STG_H) * 2u;
        const uint32_t bF = bFragBase + (uint32_t)(cur * STG_H) * 2u;

#pragma unroll
        for (int kk = 0; kk < 2; kk++) {
            const uint32_t kOff = (uint32_t)(kk * 16) * 2u;
            uint32_t af[2][4];
#pragma unroll
            for (int mi = 0; mi < 2; mi++)
                ldsm4(af[mi][0], af[mi][1], af[mi][2], af[mi][3],
                      aF + kOff + (uint32_t)(mi * 16 * APADH) * 2u);
            uint32_t bf[8][2];
#pragma unroll
            for (int j = 0; j < 4; j++)
                ldsm4(bf[2*j][0], bf[2*j+1][0], bf[2*j][1], bf[2*j+1][1],
                      bF + kOff + (uint32_t)(j * 16 * APADH) * 2u);
#pragma unroll
            for (int mi = 0; mi < 2; mi++)
#pragma unroll
                for (int ni = 0; ni < 8; ni++) {
                    asm("mma.sync.aligned.m16n8k16.row.col.f32.f16.f16.f32 "
                        "{%0,%1,%2,%3}, {%4,%5,%6,%7}, {%8,%9}, {%0,%1,%2,%3};"
                        : "+f"(acc[mi][ni][0]), "+f"(acc[mi][ni][1]),
                          "+f"(acc[mi][ni][2]), "+f"(acc[mi][ni][3])
                        : "r"(af[mi][0]), "r"(af[mi][1]),
                          "r"(af[mi][2]), "r"(af[mi][3]),
                          "r"(bf[ni][0]), "r"(bf[ni][1]));
                }
        }

        const int pf = step + NSTAGE - 1;
        if (pf < nsteps) {
            int ps = cur + NSTAGE - 1; if (ps >= NSTAGE) ps -= NSTAGE;
            const uint32_t ao = aBase + (uint32_t)(ps * STG_H) * 2u;
            const uint32_t bo = bBase + (uint32_t)(ps * STG_H) * 2u;
            CP16(ao,      Ap + pf * 32);
            CP16(ao + 16, Ap + pf * 32 + 8);
            CP16(bo,      Bp + pf * 32);
            CP16(bo + 16, Bp + pf * 32 + 8);
        }
        CP_COMMIT();
        cur = (cur + 1 == NSTAGE) ? 0 : cur + 1;
    }
    CP_WAIT0();

#pragma unroll
    for (int mi = 0; mi < 2; mi++) {
        const int r0 = bm + wm + mi * 16 + gid;
#pragma unroll
        for (int ni = 0; ni < 8; ni++) {
            const int c0 = bn + wn + ni * 8 + tig * 2;
            float bx = 0.0f, by = 0.0f;
            if (bias) { bx = bias[c0]; by = bias[c0 + 1]; }
            float2 v0, v1;
            v0.x = alpha * acc[mi][ni][0] + bx;
            v0.y = alpha * acc[mi][ni][1] + by;
            v1.x = alpha * acc[mi][ni][2] + bx;
            v1.y = alpha * acc[mi][ni][3] + by;
            if (writeMode == 0) {
                *(float2*)(Cf + (size_t)r0 * ldc + c0)       = v0;
                *(float2*)(Cf + (size_t)(r0 + 8) * ldc + c0) = v1;
            } else if (writeMode == 1) {
                *(__half2*)(Ch + (size_t)r0 * ldc + c0) =
                    __floats2half2_rn(v0.x, v0.y);
                *(__half2*)(Ch + (size_t)(r0 + 8) * ldc + c0) =
                    __floats2half2_rn(v1.x, v1.y);
            } else {
                Ch[(size_t)(c0    ) * ldc + r0    ] = __float2half_rn(v0.x);
                Ch[(size_t)(c0 + 1) * ldc + r0    ] = __float2half_rn(v0.y);
                Ch[(size_t)(c0    ) * ldc + r0 + 8] = __float2half_rn(v1.x);
                Ch[(size_t)(c0 + 1) * ldc + r0 + 8] = __float2half_rn(v1.y);
            }
        }
    }
}

__global__ __launch_bounds__(256, 2) void mma_gemm(
    const __half* __restrict__ A, int lda, long zA,
    const __half* __restrict__ B, int ldb, long zB,
    float* __restrict__ Cf, __half* __restrict__ Ch, int ldc, long zC,
    const float* __restrict__ bias, long zBias,
    float alpha, int K, int writeMode)
{
    A += (long)blockIdx.z * zA;
    B += (long)blockIdx.z * zB;
    if (Cf) Cf += (long)blockIdx.z * zC;
    if (Ch) Ch += (long)blockIdx.z * zC;
    if (bias) bias += (long)blockIdx.z * zBias;
    gemm_tile_body(A, lda, B, ldb, Cf, Ch, ldc, bias, alpha, K,
                   blockIdx.y * 128, blockIdx.x * 128, writeMode);
}

// Dense projection launch: 128 Q + 24 K + 24 V tiles = 176 CTAs.
__global__ __launch_bounds__(256, 2) void proj3_gemm(
    const __half* __restrict__ tn, const __half* __restrict__ vn,
    const __half* __restrict__ Wq, const __half* __restrict__ Wk,
    const __half* __restrict__ Wv,
    const float* __restrict__ bq, const float* __restrict__ bk,
    const float* __restrict__ bv,
    __half* __restrict__ q, __half* __restrict__ k, __half* __restrict__ vt)
{
    const int idx = blockIdx.x;
    int z, local;
    if (idx < 128)      { z = 0; local = idx; }
    else if (idx < 152) { z = 1; local = idx - 128; }
    else                { z = 2; local = idx - 152; }
    const int bn = (local & 3) * 128;
    const int bm = (local >> 2) * 128;
    const __half* A = (z == 0) ? tn : vn;
    const __half* B = (z == 0) ? Wq : (z == 1) ? Wk : Wv;
    const float* bias = (z == 0) ? bq : (z == 1) ? bk : bv;
    if (z == 2) {
        gemm_tile_body(A, EMBED, B, EMBED, nullptr, vt, VTOK, bias, 1.0f,
                       EMBED, bm, bn, 2);
    } else {
        __half* C = (z == 0) ? q : k;
        gemm_tile_body(A, EMBED, B, EMBED, nullptr, C, EMBED, bias, 1.0f,
                       EMBED, bm, bn, 1);
    }
}

// ---------------------------------------------------------------------------
__device__ __forceinline__ void ln_row(
    const float* __restrict__ x, const float* __restrict__ addx,
    const float* __restrict__ g, const float* __restrict__ b,
    float* __restrict__ outf, __half* __restrict__ outh, int row)
{
    const int t = threadIdx.x;
    const size_t base = (size_t)row * EMBED;

    float v[4];
#pragma unroll
    for (int i = 0; i < 4; i++) {
        const int c = t + i * 128;
        float val = x[base + c];
        if (addx) val += addx[base + c];
        v[i] = val;
    }
    float s  = v[0] + v[1] + v[2] + v[3];
    float s2 = v[0]*v[0] + v[1]*v[1] + v[2]*v[2] + v[3]*v[3];
#pragma unroll
    for (int o = 16; o > 0; o >>= 1) {
        s  += __shfl_xor_sync(0xffffffffu, s,  o);
        s2 += __shfl_xor_sync(0xffffffffu, s2, o);
    }
    __shared__ float ss[4], ss2[4];
    const int w = t >> 5, l = t & 31;
    if (l == 0) { ss[w] = s; ss2[w] = s2; }
    __syncthreads();
    s  = ss[0] + ss[1] + ss[2] + ss[3];
    s2 = ss2[0] + ss2[1] + ss2[2] + ss2[3];

    const float mu   = s * (1.0f / EMBED);
    const float var  = s2 * (1.0f / EMBED) - mu * mu;
    const float rstd = rsqrtf(var + 1e-5f);
#pragma unroll
    for (int i = 0; i < 4; i++) {
        const int c = t + i * 128;
        float y = (v[i] - mu) * rstd * g[c] + b[c];
        if (outf) outf[base + c] = y;
        if (outh) outh[base + c] = __float2half_rn(y);
    }
}

// Prep: LN1 text (TTOK) + LN1 video (VTOK) + fp16 weight rounding (1280).
__global__ __launch_bounds__(128) void prep_kernel(
    const float* __restrict__ text, const float* __restrict__ video,
    const float* __restrict__ ln1_g, const float* __restrict__ ln1_b,
    __half* __restrict__ tn, __half* __restrict__ vn,
    const float* __restrict__ w0, const float* __restrict__ w1,
    const float* __restrict__ w2, const float* __restrict__ w3,
    const float* __restrict__ w4,
    __half* __restrict__ o0, __half* __restrict__ o1,
    __half* __restrict__ o2, __half* __restrict__ o3,
    __half* __restrict__ o4)
{
    const int blk = blockIdx.x;
    if (blk < TTOK) {
        ln_row(text, nullptr, ln1_g, ln1_b, nullptr, tn, blk);
    } else if (blk < TTOK + VTOK) {
        ln_row(video, nullptr, ln1_g, ln1_b, nullptr, vn, blk - TTOK);
    } else {
        const int wb = blk - TTOK - VTOK;
        const int z  = wb >> 8;
        const int i  = (wb & 255) * 128 + threadIdx.x;
        const float* w = (z == 0) ? w0 : (z == 1) ? w1 : (z == 2) ? w2
                       : (z == 3) ? w3 : w4;
        __half* o = (z == 0) ? o0 : (z == 1) ? o1 : (z == 2) ? o2
                  : (z == 3) ? o3 : o4;
        float4 x = *(const float4*)(w + (size_t)i * 8);
        float4 y = *(const float4*)(w + (size_t)i * 8 + 4);
        *(__half2*)(o + (size_t)i * 8)     = __floats2half2_rn(x.x, x.y);
        *(__half2*)(o + (size_t)i * 8 + 2) = __floats2half2_rn(x.z, x.w);
        *(__half2*)(o + (size_t)i * 8 + 4) = __floats2half2_rn(y.x, y.y);
        *(__half2*)(o + (size_t)i * 8 + 6) = __floats2half2_rn(y.z, y.w);
    }
}

__global__ __launch_bounds__(128) void ln_kernel(
    const float* __restrict__ x, const float* __restrict__ addx,
    const float* __restrict__ g, const float* __restrict__ b,
    float* __restrict__ outf, __half* __restrict__ outh)
{
    ln_row(x, addx, g, b, outf, outh, blockIdx.x);
}

// ---------------------------------------------------------------------------
// Coalesced smem-staged softmax: one block = 256 groups of 12 halves.
// ---------------------------------------------------------------------------
#define SMG 256                        // groups per block
__global__ __launch_bounds__(SMG) void softmax_kernel(
    const __half* __restrict__ S, __half* __restrict__ P)
{
    __shared__ __half buf[SMG * FR];   // 6144 B
    const size_t base = (size_t)blockIdx.x * SMG * FR;
    uint32_t* b32 = (uint32_t*)buf;
    const uint32_t* src = (const uint32_t*)(S + base);
    uint32_t* dst = (uint32_t*)(P + base);
    const int t = threadIdx.x;

#pragma unroll
    for (int i = 0; i < (SMG * FR / 2) / SMG; i++)
        b32[t + i * SMG] = src[t + i * SMG];
    __syncthreads();

    float v[FR];
    float m = -3.0e38f;
#pragma unroll
    for (int i = 0; i < FR; i++) {
        v[i] = __half2float(buf[t * FR + i]);
        m = fmaxf(m, v[i]);
    }
    float sum = 0.0f;
#pragma unroll
    for (int i = 0; i < FR; i++) { v[i] = __expf(v[i] - m); sum += v[i]; }
    const float inv = 1.0f / sum;
#pragma unroll
    for (int i = 0; i < FR; i += 2)
        *(__half2*)&buf[t * FR + i] =
            __floats2half2_rn(v[i] * inv, v[i + 1] * inv);
    __syncthreads();

#pragma unroll
    for (int i = 0; i < (SMG * FR / 2) / SMG; i++)
        dst[t + i * SMG] = b32[t + i * SMG];
}

// ---------------------------------------------------------------------------
extern "C" void kernel_launch(void* const* d_in, const int* in_sizes, int n_in,
                              void* d_out, int out_size)
{
    const float* text  = (const float*)d_in[0];
    const float* video = (const float*)d_in[1];
    const float* ln1_g = (const float*)d_in[2];
    const float* ln1_b = (const float*)d_in[3];
    const float* Wq = (const float*)d_in[4];
    const float* bq = (const float*)d_in[5];
    const float* Wk = (const float*)d_in[6];
    const float* bk = (const float*)d_in[7];
    const float* Wv = (const float*)d_in[8];
    const float* bv = (const float*)d_in[9];
    const float* Wo = (const float*)d_in[10];
    const float* bo = (const float*)d_in[11];
    const float* Wl = (const float*)d_in[12];
    const float* bl = (const float*)d_in[13];
    const float* ln2_g = (const float*)d_in[14];
    const float* ln2_b = (const float*)d_in[15];
    const float* ln3_g = (const float*)d_in[16];
    const float* ln3_b = (const float*)d_in[17];
    float* out = (float*)d_out;

    cudaFuncSetAttribute(mma_gemm,
        cudaFuncAttributeMaxDynamicSharedMemorySize, SMEM_BYTES);
    cudaFuncSetAttribute(proj3_gemm,
        cudaFuncAttributeMaxDynamicSharedMemorySize, SMEM_BYTES);

    __half *tn, *vn, *q, *k, *vt, *sh, *p, *attn, *orr;
    __half *wqr, *wkr, *wvr, *wor, *wlr;
    float *opre, *o, *lin;
    cudaGetSymbolAddress((void**)&tn,   g_tn);
    cudaGetSymbolAddress((void**)&vn,   g_vn);
    cudaGetSymbolAddress((void**)&q,    g_q);
    cudaGetSymbolAddress((void**)&k,    g_k);
    cudaGetSymbolAddress((void**)&vt,   g_vt);
    cudaGetSymbolAddress((void**)&sh,   g_sh);
    cudaGetSymbolAddress((void**)&p,    g_p);
    cudaGetSymbolAddress((void**)&attn, g_attn);
    cudaGetSymbolAddress((void**)&opre, g_opre);
    cudaGetSymbolAddress((void**)&o,    g_o);
    cudaGetSymbolAddress((void**)&orr,  g_or);
    cudaGetSymbolAddress((void**)&lin,  g_lin);
    cudaGetSymbolAddress((void**)&wqr,  g_wqr);
    cudaGetSymbolAddress((void**)&wkr,  g_wkr);
    cudaGetSymbolAddress((void**)&wvr,  g_wvr);
    cudaGetSymbolAddress((void**)&wor,  g_wor);
    cudaGetSymbolAddress((void**)&wlr,  g_wlr);

    // 1) fused prep
    prep_kernel<<<TTOK + VTOK + 1280, 128>>>(
        text, video, ln1_g, ln1_b, tn, vn,
        Wq, Wk, Wv, Wo, Wl, wqr, wkr, wvr, wor, wlr);

    // 2) Q/K/V projections (V transposed into vt), 176 CTAs
    proj3_gemm<<<176, 256, SMEM_BYTES>>>(
        tn, vn, wqr, wkr, wvr, bq, bk, bv, q, k, vt);

    // 3) logits -> HALF sh (384 CTAs)
    mma_gemm<<<dim3(6, 32, 2), 256, SMEM_BYTES>>>(
        q, EMBED, HDIM, k, EMBED, HDIM,
        nullptr, sh, VTOK, (long)TTOK * VTOK, nullptr, 0,
        1.0f / 16.0f, HDIM, 1);

    // 4) coalesced softmax: 524288 groups / 256 = 2048 blocks
    softmax_kernel<<<HEADS * TTOK * NV / SMG, SMG>>>(sh, p);

    // 5) attn_h = P_h @ V_h / 64 -> half attn (128 CTAs)
    mma_gemm<<<dim3(2, 32, 2), 256, SMEM_BYTES>>>(
        p, VTOK, (long)TTOK * VTOK, vt, VTOK, (long)HDIM * VTOK,
        nullptr, attn, EMBED, HDIM, nullptr, 0,
        1.0f / 64.0f, VTOK, 1);

    // 6) output projection -> f32 opre; LN2 -> o (f32) + orr (half)
    mma_gemm<<<dim3(4, 32, 1), 256, SMEM_BYTES>>>(
        attn, EMBED, 0, wor, EMBED, 0,
        opre, nullptr, EMBED, 0, bo, 0, 1.0f, EMBED, 0);
    ln_kernel<<<TTOK, 128>>>(opre, nullptr, ln2_g, ln2_b, o, orr);

    // 7) linear -> f32 lin; LN3(o + lin) -> out
    mma_gemm<<<dim3(4, 32, 1), 256, SMEM_BYTES>>>(
        orr, EMBED, 0, wlr, EMBED, 0,
        lin, nullptr, EMBED, 0, bl, 0, 1.0f, EMBED, 0);
    ln_kernel<<<TTOK, 128>>>(o, lin, ln3_g, ln3_b, out, nullptr);
}